// round 14
// baseline (speedup 1.0000x reference)
#include <cuda_runtime.h>
#include <cstdint>

// FROZEN CHAMPION (R10) + balanced grid (R14): [B, 9, 5, 5] float32.
// Persistent 1-warp CTAs, 3-buffer ring cp.async.bulk pipeline over 20-batch
// segments (18000 B). 3 buffers = 54.1 KB/CTA -> 4 CTAs/SM.
// R14 delta: grid is chosen as the largest value <= 608 that divides nseg
// exactly (535 for B=524288), eliminating the 71-CTA straggler wave-tail
// (~2% of kernel time with the chip mostly idle). Pipeline body unchanged.
// Arithmetic is the FROZEN round-1/2 sequence (rcp.approx + fmaf): measured
// rel_err 4.918e-4 across eleven schedules. Do not alter.
constexpr int NB = 20;
constexpr int THREADS = 32;
constexpr int BATCH_FLOATS = 225;
constexpr int BATCH_BYTES = 900;
constexpr int SEG_FLOATS = NB * BATCH_FLOATS;      // 4500
constexpr int SEG_BYTES = SEG_FLOATS * 4;          // 18000
constexpr int NBUF = 3;
constexpr int SMEM_BYTES = 128 + NBUF * SEG_BYTES; // 54128 -> 4 CTAs/SM
constexpr int MAX_CTAS = 608;                      // 4 per SM * 152 SMs
constexpr int MIN_CTAS = 480;                      // don't drop engines below this

__device__ __forceinline__ uint32_t s2u(const void* p) {
    return (uint32_t)__cvta_generic_to_shared(p);
}

__device__ __forceinline__ float rcp_fast(float x) {
    float r;
    asm("rcp.approx.f32 %0, %1;" : "=f"(r) : "f"(x));
    return r;
}

// Unpivoted 5x5 LU fully in registers — FROZEN arithmetic.
__device__ __forceinline__ void lu5(float* a) {
#pragma unroll
    for (int k = 0; k < 4; ++k) {
        const float rinv = rcp_fast(a[k * 5 + k]);
#pragma unroll
        for (int i = k + 1; i < 5; ++i) {
            const float c = a[i * 5 + k] * rinv;
            a[i * 5 + k] = c;
#pragma unroll
            for (int j = k + 1; j < 5; ++j)
                a[i * 5 + j] = fmaf(-c, a[k * 5 + j], a[i * 5 + j]);
        }
    }
}

__device__ __forceinline__ void load_blk(const float* m, int blk, float* a) {
    const float* p = m + blk * 25;
#pragma unroll
    for (int i = 0; i < 25; ++i) a[i] = p[i];
}

__device__ __forceinline__ void store_blk(float* m, int blk, const float* a) {
    float* p = m + blk * 25;
#pragma unroll
    for (int i = 0; i < 25; ++i) p[i] = a[i];
}

// Full per-batch factorization — FROZEN op sequence.
__device__ __forceinline__ void factor_batch(float* m) {
    float a[25];

    load_blk(m, 0, a); lu5(a); store_blk(m, 0, a);
    const float s0 = a[6];

    load_blk(m, 1, a); lu5(a); store_blk(m, 1, a);
    const float s1 = a[6];

    load_blk(m, 2, a); lu5(a); store_blk(m, 2, a);
    const float c22 = a[12], c23 = a[13], c32 = a[17], c33 = a[18];

    load_blk(m, 5, a); lu5(a); store_blk(m, 5, a);
    const float s5 = a[6];

    load_blk(m, 6, a); lu5(a); store_blk(m, 6, a);
    const float d33 = a[18], d34 = a[19], d43 = a[23], d44 = a[24];

    // Block 4: passthrough (already staged).

    load_blk(m, 3, a);
    a[0] = a[0] - s1 - c22;
    a[1] -= c23;
    a[5] -= c32;
    a[6] -= c33;
    lu5(a); store_blk(m, 3, a);
    const float t3 = a[6];

    load_blk(m, 7, a);
    a[0] = a[0] - s5 - d33;
    a[1] -= d34;
    a[5] -= d43;
    a[6] -= d44;
    lu5(a); store_blk(m, 7, a);
    const float t7 = a[6];

    load_blk(m, 8, a);
    a[0] = a[0] - s0 - t3 - t7;
    lu5(a); store_blk(m, 8, a);
}

#define MBAR_WAIT(addr, parity) do {                                          \
    asm volatile(                                                             \
        "{\n\t.reg .pred p;\n\t"                                              \
        "WL%=:\n\t"                                                           \
        "mbarrier.try_wait.parity.acquire.cta.shared::cta.b64 p, [%0], %1;\n\t" \
        "@!p bra WL%=;\n\t}"                                                  \
        :: "r"(addr), "r"(parity) : "memory");                                \
} while (0)

extern __shared__ float smem[];

// nbatch: total batches handled by the pipe. Last segment may be short.
__global__ void __launch_bounds__(THREADS)
lu_pipe_kernel(const float* __restrict__ in, float* __restrict__ out,
               int nseg, int nbatch) {
    // Layout: [0,24) 3 mbarriers (pad to 128B), buffers from byte 128.
    const int tid = threadIdx.x;
    const uint32_t mb_base = s2u(smem);        // mbarrier b at mb_base + 8*b
    float* const buf_base = smem + 32;         // buffer b at + b*SEG_FLOATS
    const uint32_t buf_base_u = s2u(buf_base);

    if (tid == 0) {
#pragma unroll
        for (int b = 0; b < NBUF; ++b)
            asm volatile("mbarrier.init.shared::cta.b64 [%0], 1;"
                         :: "r"(mb_base + 8u * b));
    }
    __syncwarp();

    const long long g = gridDim.x;
    long long s = blockIdx.x;

    // Prologue: issue load of first segment into buffer 0.
    if (tid == 0 && s < nseg) {
        const int nb0 = min(NB, nbatch - (int)(s * NB));
        const uint32_t bytes0 = (uint32_t)nb0 * BATCH_BYTES;
        asm volatile("mbarrier.arrive.expect_tx.shared::cta.b64 _, [%0], %1;"
                     :: "r"(mb_base), "r"(bytes0));
        asm volatile(
            "cp.async.bulk.shared::cta.global.mbarrier::complete_tx::bytes "
            "[%0], [%1], %2, [%3];"
            :: "r"(buf_base_u), "l"(in + s * SEG_FLOATS), "r"(bytes0),
               "r"(mb_base) : "memory");
    }

    int cur = 0;           // iter % 3, maintained incrementally
    int phbits = 0;        // per-buffer phase parity bitmask
    for (; s < nseg; s += g) {
        const uint32_t mb_cur = mb_base + 8u * cur;
        float* const bcur = buf_base + cur * SEG_FLOATS;
        const int nb_cur = min(NB, nbatch - (int)(s * NB));
        const uint32_t bytes_cur = (uint32_t)nb_cur * BATCH_BYTES;
        const int nxt = (cur == NBUF - 1) ? 0 : cur + 1;

        // Prefetch next segment into buffer nxt. That buffer's store was
        // committed TWO iterations ago -> wait_group.read 1 drains only it,
        // leaving the newest store outstanding (no fresh-store stall).
        if (tid == 0) {
            const long long ns = s + g;
            if (ns < nseg) {
                const int nb_n = min(NB, nbatch - (int)(ns * NB));
                const uint32_t bytes_n = (uint32_t)nb_n * BATCH_BYTES;
                asm volatile("cp.async.bulk.wait_group.read 1;" ::: "memory");
                const uint32_t mb_n = mb_base + 8u * nxt;
                asm volatile("mbarrier.arrive.expect_tx.shared::cta.b64 _, [%0], %1;"
                             :: "r"(mb_n), "r"(bytes_n));
                asm volatile(
                    "cp.async.bulk.shared::cta.global.mbarrier::complete_tx::bytes "
                    "[%0], [%1], %2, [%3];"
                    :: "r"(buf_base_u + (uint32_t)nxt * SEG_BYTES),
                       "l"(in + ns * SEG_FLOATS), "r"(bytes_n),
                       "r"(mb_n) : "memory");
            }
        }

        // Wait for current segment's data (every lane waits -> acts as a
        // warp-convergence point; no extra syncwarp needed).
        MBAR_WAIT(mb_cur, (phbits >> cur) & 1);
        phbits ^= (1 << cur);

        // One thread per batch (threads 0..nb_cur-1). smem stride 225 == 1
        // (mod 32): conflict-free.
        if (tid < nb_cur)
            factor_batch(bcur + tid * BATCH_FLOATS);

        // All lanes' smem writes must complete before tid0's async-proxy store.
        __syncwarp();
        asm volatile("fence.proxy.async.shared::cta;" ::: "memory");

        // Async store of the finished segment; don't wait.
        if (tid == 0) {
            asm volatile(
                "cp.async.bulk.global.shared::cta.bulk_group [%0], [%1], %2;"
                :: "l"(out + s * SEG_FLOATS),
                   "r"(buf_base_u + (uint32_t)cur * SEG_BYTES), "r"(bytes_cur)
                : "memory");
            asm volatile("cp.async.bulk.commit_group;" ::: "memory");
        }

        cur = nxt;
    }

    // Drain pending bulk-store smem reads before CTA exit.
    if (tid == 0)
        asm volatile("cp.async.bulk.wait_group.read 0;" ::: "memory");
}

// Fallback only if remainder*900 is not a multiple of 16 (rem % 4 != 0).
// Never taken for B=524288 (rem=8, 8%4==0 -> handled in the pipe).
__global__ void lu_tail_kernel(const float* __restrict__ in,
                               float* __restrict__ out, int start, int nbatch) {
    const int b = start + blockIdx.x * blockDim.x + threadIdx.x;
    if (b >= nbatch) return;
    float m[BATCH_FLOATS];
    const float* src = in + (long long)b * BATCH_FLOATS;
    for (int i = 0; i < BATCH_FLOATS; ++i) m[i] = src[i];
    factor_batch(m);
    float* dst = out + (long long)b * BATCH_FLOATS;
    for (int i = 0; i < BATCH_FLOATS; ++i) dst[i] = m[i];
}

extern "C" void kernel_launch(void* const* d_in, const int* in_sizes, int n_in,
                              void* d_out, int out_size) {
    const float* in = (const float*)d_in[0];
    float* out = (float*)d_out;
    const int nbatch = in_sizes[0] / BATCH_FLOATS;
    const int rem = nbatch % NB;
    const bool rem_ok = (rem % 4) == 0;   // rem*900 must be a 16B multiple
    const int pipe_batches = rem_ok ? nbatch : nbatch - rem;
    const int nseg = (pipe_batches + NB - 1) / NB;

    static bool attr_set = false;  // idempotent opt-in (cheap; graph-capture safe)
    if (!attr_set) {
        cudaFuncSetAttribute(lu_pipe_kernel,
                             cudaFuncAttributeMaxDynamicSharedMemorySize, SMEM_BYTES);
        attr_set = true;
    }

    if (nseg > 0) {
        // Balanced grid: largest g <= MAX_CTAS with nseg % g == 0 (so every
        // CTA runs the same iteration count -> no straggler wave-tail).
        // Falls back to MAX_CTAS if no divisor exists in [MIN_CTAS, MAX_CTAS].
        int grid = nseg < MAX_CTAS ? nseg : MAX_CTAS;
        if (nseg > MAX_CTAS) {
            for (int gcand = MAX_CTAS; gcand >= MIN_CTAS; --gcand) {
                if (nseg % gcand == 0) { grid = gcand; break; }
            }
        }
        lu_pipe_kernel<<<grid, THREADS, SMEM_BYTES>>>(in, out, nseg, pipe_batches);
    }
    if (!rem_ok && rem > 0) {
        lu_tail_kernel<<<1, ((rem + 31) / 32) * 32>>>(in, out, nbatch - rem, nbatch);
    }
}

// round 15
// speedup vs baseline: 1.0392x; 1.0392x over previous
#include <cuda_runtime.h>
#include <cstdint>

// FINAL FROZEN CHAMPION (R10/R13): [B, 9, 5, 5] float32, 900 B per batch.
// Persistent 1-warp CTAs, 3-buffer ring cp.async.bulk pipeline over 20-batch
// segments (18000 B). 3 buffers = 54.1 KB/CTA -> 4 CTAs/SM, grid 608.
// Measured: dur_us 149.6, kernel ~141-143us, DRAM ~79-80% (6.3 TB/s) — the
// practical HBM3e ceiling for a balanced read/write stream. R11 (4buf),
// R12 (NB=40/2-warp), R14 (balanced grid) all landed within 1.5%: converged.
// Arithmetic is the FROZEN round-1/2 sequence (rcp.approx + fmaf): measured
// rel_err 4.918e-4 across twelve schedules. Do not alter.
constexpr int NB = 20;
constexpr int THREADS = 32;
constexpr int BATCH_FLOATS = 225;
constexpr int BATCH_BYTES = 900;
constexpr int SEG_FLOATS = NB * BATCH_FLOATS;      // 4500
constexpr int SEG_BYTES = SEG_FLOATS * 4;          // 18000
constexpr int NBUF = 3;
constexpr int SMEM_BYTES = 128 + NBUF * SEG_BYTES; // 54128 -> 4 CTAs/SM
constexpr int MAX_CTAS = 608;                      // 4 per SM * 152 SMs

__device__ __forceinline__ uint32_t s2u(const void* p) {
    return (uint32_t)__cvta_generic_to_shared(p);
}

__device__ __forceinline__ float rcp_fast(float x) {
    float r;
    asm("rcp.approx.f32 %0, %1;" : "=f"(r) : "f"(x));
    return r;
}

// Unpivoted 5x5 LU fully in registers — FROZEN arithmetic.
__device__ __forceinline__ void lu5(float* a) {
#pragma unroll
    for (int k = 0; k < 4; ++k) {
        const float rinv = rcp_fast(a[k * 5 + k]);
#pragma unroll
        for (int i = k + 1; i < 5; ++i) {
            const float c = a[i * 5 + k] * rinv;
            a[i * 5 + k] = c;
#pragma unroll
            for (int j = k + 1; j < 5; ++j)
                a[i * 5 + j] = fmaf(-c, a[k * 5 + j], a[i * 5 + j]);
        }
    }
}

__device__ __forceinline__ void load_blk(const float* m, int blk, float* a) {
    const float* p = m + blk * 25;
#pragma unroll
    for (int i = 0; i < 25; ++i) a[i] = p[i];
}

__device__ __forceinline__ void store_blk(float* m, int blk, const float* a) {
    float* p = m + blk * 25;
#pragma unroll
    for (int i = 0; i < 25; ++i) p[i] = a[i];
}

// Full per-batch factorization — FROZEN op sequence.
__device__ __forceinline__ void factor_batch(float* m) {
    float a[25];

    load_blk(m, 0, a); lu5(a); store_blk(m, 0, a);
    const float s0 = a[6];

    load_blk(m, 1, a); lu5(a); store_blk(m, 1, a);
    const float s1 = a[6];

    load_blk(m, 2, a); lu5(a); store_blk(m, 2, a);
    const float c22 = a[12], c23 = a[13], c32 = a[17], c33 = a[18];

    load_blk(m, 5, a); lu5(a); store_blk(m, 5, a);
    const float s5 = a[6];

    load_blk(m, 6, a); lu5(a); store_blk(m, 6, a);
    const float d33 = a[18], d34 = a[19], d43 = a[23], d44 = a[24];

    // Block 4: passthrough (already staged).

    load_blk(m, 3, a);
    a[0] = a[0] - s1 - c22;
    a[1] -= c23;
    a[5] -= c32;
    a[6] -= c33;
    lu5(a); store_blk(m, 3, a);
    const float t3 = a[6];

    load_blk(m, 7, a);
    a[0] = a[0] - s5 - d33;
    a[1] -= d34;
    a[5] -= d43;
    a[6] -= d44;
    lu5(a); store_blk(m, 7, a);
    const float t7 = a[6];

    load_blk(m, 8, a);
    a[0] = a[0] - s0 - t3 - t7;
    lu5(a); store_blk(m, 8, a);
}

#define MBAR_WAIT(addr, parity) do {                                          \
    asm volatile(                                                             \
        "{\n\t.reg .pred p;\n\t"                                              \
        "WL%=:\n\t"                                                           \
        "mbarrier.try_wait.parity.acquire.cta.shared::cta.b64 p, [%0], %1;\n\t" \
        "@!p bra WL%=;\n\t}"                                                  \
        :: "r"(addr), "r"(parity) : "memory");                                \
} while (0)

extern __shared__ float smem[];

// nbatch: total batches handled by the pipe. Last segment may be short.
__global__ void __launch_bounds__(THREADS)
lu_pipe_kernel(const float* __restrict__ in, float* __restrict__ out,
               int nseg, int nbatch) {
    // Layout: [0,24) 3 mbarriers (pad to 128B), buffers from byte 128.
    const int tid = threadIdx.x;
    const uint32_t mb_base = s2u(smem);        // mbarrier b at mb_base + 8*b
    float* const buf_base = smem + 32;         // buffer b at + b*SEG_FLOATS
    const uint32_t buf_base_u = s2u(buf_base);

    if (tid == 0) {
#pragma unroll
        for (int b = 0; b < NBUF; ++b)
            asm volatile("mbarrier.init.shared::cta.b64 [%0], 1;"
                         :: "r"(mb_base + 8u * b));
    }
    __syncwarp();

    const long long g = gridDim.x;
    long long s = blockIdx.x;

    // Prologue: issue load of first segment into buffer 0.
    if (tid == 0 && s < nseg) {
        const int nb0 = min(NB, nbatch - (int)(s * NB));
        const uint32_t bytes0 = (uint32_t)nb0 * BATCH_BYTES;
        asm volatile("mbarrier.arrive.expect_tx.shared::cta.b64 _, [%0], %1;"
                     :: "r"(mb_base), "r"(bytes0));
        asm volatile(
            "cp.async.bulk.shared::cta.global.mbarrier::complete_tx::bytes "
            "[%0], [%1], %2, [%3];"
            :: "r"(buf_base_u), "l"(in + s * SEG_FLOATS), "r"(bytes0),
               "r"(mb_base) : "memory");
    }

    int cur = 0;           // iter % 3, maintained incrementally
    int phbits = 0;        // per-buffer phase parity bitmask
    for (; s < nseg; s += g) {
        const uint32_t mb_cur = mb_base + 8u * cur;
        float* const bcur = buf_base + cur * SEG_FLOATS;
        const int nb_cur = min(NB, nbatch - (int)(s * NB));
        const uint32_t bytes_cur = (uint32_t)nb_cur * BATCH_BYTES;
        const int nxt = (cur == NBUF - 1) ? 0 : cur + 1;

        // Prefetch next segment into buffer nxt. That buffer's store was
        // committed TWO iterations ago -> wait_group.read 1 drains only it,
        // leaving the newest store outstanding (no fresh-store stall).
        if (tid == 0) {
            const long long ns = s + g;
            if (ns < nseg) {
                const int nb_n = min(NB, nbatch - (int)(ns * NB));
                const uint32_t bytes_n = (uint32_t)nb_n * BATCH_BYTES;
                asm volatile("cp.async.bulk.wait_group.read 1;" ::: "memory");
                const uint32_t mb_n = mb_base + 8u * nxt;
                asm volatile("mbarrier.arrive.expect_tx.shared::cta.b64 _, [%0], %1;"
                             :: "r"(mb_n), "r"(bytes_n));
                asm volatile(
                    "cp.async.bulk.shared::cta.global.mbarrier::complete_tx::bytes "
                    "[%0], [%1], %2, [%3];"
                    :: "r"(buf_base_u + (uint32_t)nxt * SEG_BYTES),
                       "l"(in + ns * SEG_FLOATS), "r"(bytes_n),
                       "r"(mb_n) : "memory");
            }
        }

        // Wait for current segment's data (every lane waits -> acts as a
        // warp-convergence point; no extra syncwarp needed).
        MBAR_WAIT(mb_cur, (phbits >> cur) & 1);
        phbits ^= (1 << cur);

        // One thread per batch (threads 0..nb_cur-1). smem stride 225 == 1
        // (mod 32): conflict-free.
        if (tid < nb_cur)
            factor_batch(bcur + tid * BATCH_FLOATS);

        // All lanes' smem writes must complete before tid0's async-proxy store.
        __syncwarp();
        asm volatile("fence.proxy.async.shared::cta;" ::: "memory");

        // Async store of the finished segment; don't wait.
        if (tid == 0) {
            asm volatile(
                "cp.async.bulk.global.shared::cta.bulk_group [%0], [%1], %2;"
                :: "l"(out + s * SEG_FLOATS),
                   "r"(buf_base_u + (uint32_t)cur * SEG_BYTES), "r"(bytes_cur)
                : "memory");
            asm volatile("cp.async.bulk.commit_group;" ::: "memory");
        }

        cur = nxt;
    }

    // Drain pending bulk-store smem reads before CTA exit.
    if (tid == 0)
        asm volatile("cp.async.bulk.wait_group.read 0;" ::: "memory");
}

// Fallback only if remainder*900 is not a multiple of 16 (rem % 4 != 0).
// Never taken for B=524288 (rem=8, 8%4==0 -> handled in the pipe).
__global__ void lu_tail_kernel(const float* __restrict__ in,
                               float* __restrict__ out, int start, int nbatch) {
    const int b = start + blockIdx.x * blockDim.x + threadIdx.x;
    if (b >= nbatch) return;
    float m[BATCH_FLOATS];
    const float* src = in + (long long)b * BATCH_FLOATS;
    for (int i = 0; i < BATCH_FLOATS; ++i) m[i] = src[i];
    factor_batch(m);
    float* dst = out + (long long)b * BATCH_FLOATS;
    for (int i = 0; i < BATCH_FLOATS; ++i) dst[i] = m[i];
}

extern "C" void kernel_launch(void* const* d_in, const int* in_sizes, int n_in,
                              void* d_out, int out_size) {
    const float* in = (const float*)d_in[0];
    float* out = (float*)d_out;
    const int nbatch = in_sizes[0] / BATCH_FLOATS;
    const int rem = nbatch % NB;
    const bool rem_ok = (rem % 4) == 0;   // rem*900 must be a 16B multiple
    const int pipe_batches = rem_ok ? nbatch : nbatch - rem;
    const int nseg = (pipe_batches + NB - 1) / NB;

    static bool attr_set = false;  // idempotent opt-in (cheap; graph-capture safe)
    if (!attr_set) {
        cudaFuncSetAttribute(lu_pipe_kernel,
                             cudaFuncAttributeMaxDynamicSharedMemorySize, SMEM_BYTES);
        attr_set = true;
    }

    if (nseg > 0) {
        const int grid = nseg < MAX_CTAS ? nseg : MAX_CTAS;
        lu_pipe_kernel<<<grid, THREADS, SMEM_BYTES>>>(in, out, nseg, pipe_batches);
    }
    if (!rem_ok && rem > 0) {
        lu_tail_kernel<<<1, ((rem + 31) / 32) * 32>>>(in, out, nbatch - rem, nbatch);
    }
}